// round 13
// baseline (speedup 1.0000x reference)
#include <cuda_runtime.h>

#define N_NODES 500000
#define N_EDGES 16000000
#define FULL 0xffffffffu
#define CAP_LOG 7                              // 128 slots per node bucket
#define CAP (1 << CAP_LOG)

// ---------------- device scratch (static; no allocation) ----------------
__device__ int   g_cnt[N_NODES];               // in-degree (also fill cursor)
__device__ int   g_col[(size_t)N_NODES * CAP]; // bucketized CSR: row i at i*CAP
__device__ float g_pa[(size_t)N_NODES * 8];    // projected features (32B records)
__device__ float g_pb[(size_t)N_NODES * 8];
__device__ float g_sa[(size_t)N_NODES * 8];    // precomputed self terms
__device__ float g_sb[(size_t)N_NODES * 8];

// gather load, L1 no-allocate (table >> L1; skip tag-allocate/fill work)
__device__ __forceinline__ float4 ldg_na4(const float4* a) {
    float4 v;
    asm("ld.global.nc.L1::no_allocate.v4.f32 {%0,%1,%2,%3}, [%4];"
        : "=f"(v.x), "=f"(v.y), "=f"(v.z), "=f"(v.w) : "l"(a));
    return v;
}
__device__ __forceinline__ float ldg_na1(const float* a) {
    float v;
    asm("ld.global.nc.L1::no_allocate.f32 %0, [%1];" : "=f"(v) : "l"(a));
    return v;
}

// ---------------- fused build: CSR fill (blocks [0,nfill)) + layer-0 proj (rest) ----------------
__global__ void __launch_bounds__(256)
k_build(const int* __restrict__ ei, int E, int nfill,
        const float* __restrict__ x,
        const float* __restrict__ Wl1, const float* __restrict__ Wr1,
        const float* __restrict__ b1,
        float* __restrict__ p0, float* __restrict__ s0) {
    if (blockIdx.x < nfill) {
        int e4 = (blockIdx.x * blockDim.x + threadIdx.x) * 4;
        if (e4 < E) {
            int4 d = *reinterpret_cast<const int4*>(ei + E + e4);  // dst
            int4 s = *reinterpret_cast<const int4*>(ei + e4);      // src
            int q0 = atomicAdd(&g_cnt[d.x], 1); g_col[((size_t)d.x << CAP_LOG) + q0] = s.x;
            int q1 = atomicAdd(&g_cnt[d.y], 1); g_col[((size_t)d.y << CAP_LOG) + q1] = s.y;
            int q2 = atomicAdd(&g_cnt[d.z], 1); g_col[((size_t)d.z << CAP_LOG) + q2] = s.z;
            int q3 = atomicAdd(&g_cnt[d.w], 1); g_col[((size_t)d.w << CAP_LOG) + q3] = s.w;
        }
        return;
    }
    // ---- layer-0 projection part ----
    __shared__ float sW[105];                 // Wl1(50) | Wr1(50) | b1(5)
    int t = threadIdx.x;
    if (t < 50)       sW[t] = Wl1[t];
    else if (t < 100) sW[t] = Wr1[t - 50];
    else if (t < 105) sW[t] = b1[t - 100];
    __syncthreads();

    int i = (blockIdx.x - nfill) * blockDim.x + t;
    if (i >= N_NODES) return;

    float xv[10];
    #pragma unroll
    for (int j = 0; j < 10; j++) xv[j] = x[(size_t)i * 10 + j];

    float pv[5], sv[5];
    #pragma unroll
    for (int d = 0; d < 5; d++) {
        float a = 0.f, bsum = sW[100 + d];
        #pragma unroll
        for (int j = 0; j < 10; j++) {
            a    = fmaf(sW[d * 10 + j],      xv[j], a);
            bsum = fmaf(sW[50 + d * 10 + j], xv[j], bsum);
        }
        pv[d] = a; sv[d] = bsum;
    }
    float4* pr = reinterpret_cast<float4*>(p0 + (size_t)i * 8);
    float4* sr = reinterpret_cast<float4*>(s0 + (size_t)i * 8);
    pr[0] = make_float4(pv[0], pv[1], pv[2], pv[3]);
    pr[1] = make_float4(pv[4], 0.f, 0.f, 0.f);
    sr[0] = make_float4(sv[0], sv[1], sv[2], sv[3]);
    sr[1] = make_float4(sv[4], 0.f, 0.f, 0.f);
}

// ---------------- fused 5-dim layer, TWO nodes per warp (round-10 proven) ----------------
// Gather at the L1tex replay floor: lane pairs load float4 halves of a node's
// 32B record (16 edges/LDG.128, 1 line/edge), 2x unrolled (4 gather LDGs in
// flight per warp), L1::no_allocate on the gathers.
template<int POUT>
__global__ void __launch_bounds__(256)
k_agg5(const float* __restrict__ p, const float* __restrict__ self,
       float* __restrict__ pout, float* __restrict__ sout,
       const float* __restrict__ Wl, const float* __restrict__ Wr,
       const float* __restrict__ b) {
    __shared__ float sWl[POUT * 5], sWr[POUT * 5], sb[POUT];
    int t = threadIdx.x;
    if (t < POUT * 5)                 sWl[t]      = Wl[t];
    if (t >= 32 && t < 32 + POUT * 5) sWr[t - 32] = Wr[t - 32];
    if (t >= 64 && t < 64 + POUT)     sb[t - 64]  = b[t - 64];
    __syncthreads();

    int warp = t >> 5, lane = t & 31;
    int i0 = (blockIdx.x * (blockDim.x >> 5) + warp) * 2;
    if (i0 >= N_NODES) return;

    int2 dg = *reinterpret_cast<const int2*>(g_cnt + i0);   // degA, degB (i0 even)
    int degA = dg.x, degB = dg.y;
    int startA = i0 << CAP_LOG, startB = (i0 + 1) << CAP_LOG;
    int endA = startA + degA, endB = startB + degB;

    int half = lane & 1;                   // 0: p[0..3], 1: p[4..7]
    int epos = lane >> 1;                  // edge slot 0..15

    float4 accA = make_float4(0.f, 0.f, 0.f, 0.f);
    float4 accB = make_float4(0.f, 0.f, 0.f, 0.f);
    int jA = startA + epos, jB = startB + epos;
    while (jA < endA || jB < endB) {
        int sA0 = (jA      < endA) ? __ldg(g_col + jA)      : -1;
        int sA1 = (jA + 16 < endA) ? __ldg(g_col + jA + 16) : -1;
        int sB0 = (jB      < endB) ? __ldg(g_col + jB)      : -1;
        int sB1 = (jB + 16 < endB) ? __ldg(g_col + jB + 16) : -1;
        if (sA0 >= 0) {
            float4 v = ldg_na4(reinterpret_cast<const float4*>(p + (size_t)sA0 * 8) + half);
            accA.x += v.x; accA.y += v.y; accA.z += v.z; accA.w += v.w;
        }
        if (sB0 >= 0) {
            float4 v = ldg_na4(reinterpret_cast<const float4*>(p + (size_t)sB0 * 8) + half);
            accB.x += v.x; accB.y += v.y; accB.z += v.z; accB.w += v.w;
        }
        if (sA1 >= 0) {
            float4 v = ldg_na4(reinterpret_cast<const float4*>(p + (size_t)sA1 * 8) + half);
            accA.x += v.x; accA.y += v.y; accA.z += v.z; accA.w += v.w;
        }
        if (sB1 >= 0) {
            float4 v = ldg_na4(reinterpret_cast<const float4*>(p + (size_t)sB1 * 8) + half);
            accB.x += v.x; accB.y += v.y; accB.z += v.z; accB.w += v.w;
        }
        jA += 32; jB += 32;
    }

    int h    = lane >> 4;                  // which node this half-warp finishes
    int l16  = lane & 15;
    int base = lane & 16;
    int i    = i0 + h;
    int deg  = h ? degB : degA;

    // self load early: latency hides under the shfl-reduction chain below
    float sv  = (l16 < 5) ? __ldg(self + (size_t)i * 8 + l16) : 0.f;

    // fold across halves (xor 16 preserves lane parity)
    accA.x += __shfl_xor_sync(FULL, accA.x, 16);
    accA.y += __shfl_xor_sync(FULL, accA.y, 16);
    accA.z += __shfl_xor_sync(FULL, accA.z, 16);
    accA.w += __shfl_xor_sync(FULL, accA.w, 16);
    accB.x += __shfl_xor_sync(FULL, accB.x, 16);
    accB.y += __shfl_xor_sync(FULL, accB.y, 16);
    accB.z += __shfl_xor_sync(FULL, accB.z, 16);
    accB.w += __shfl_xor_sync(FULL, accB.w, 16);

    // select this half-warp's node, then 3 parity-preserving levels
    float4 u;
    u.x = h ? accB.x : accA.x;
    u.y = h ? accB.y : accA.y;
    u.z = h ? accB.z : accA.z;
    u.w = h ? accB.w : accA.w;
    #pragma unroll
    for (int off = 2; off <= 8; off <<= 1) {
        u.x += __shfl_xor_sync(FULL, u.x, off);
        u.y += __shfl_xor_sync(FULL, u.y, off);
        u.z += __shfl_xor_sync(FULL, u.z, off);
        u.w += __shfl_xor_sync(FULL, u.w, off);
    }

    float s0 = __shfl_sync(FULL, u.x, base);         // even lane: dims0-3
    float s1 = __shfl_sync(FULL, u.y, base);
    float s2 = __shfl_sync(FULL, u.z, base);
    float s3 = __shfl_sync(FULL, u.w, base);
    float s4 = __shfl_sync(FULL, u.x, base | 1);     // odd lane: dim4

    float inv = 1.0f / (float)max(deg, 1);

    float f0 = fmaxf(fmaf(s0, inv, __shfl_sync(FULL, sv, base + 0)), 0.f);
    float f1 = fmaxf(fmaf(s1, inv, __shfl_sync(FULL, sv, base + 1)), 0.f);
    float f2 = fmaxf(fmaf(s2, inv, __shfl_sync(FULL, sv, base + 2)), 0.f);
    float f3 = fmaxf(fmaf(s3, inv, __shfl_sync(FULL, sv, base + 3)), 0.f);
    float f4 = fmaxf(fmaf(s4, inv, __shfl_sync(FULL, sv, base + 4)), 0.f);

    if (POUT == 5) {
        if (l16 < 8) {
            float w = 0.f;
            if (l16 < 5) {
                const float* r = sWl + l16 * 5;
                w = fmaf(r[0], f0, fmaf(r[1], f1, fmaf(r[2], f2, fmaf(r[3], f3, r[4] * f4))));
            }
            pout[(size_t)i * 8 + l16] = w;   // lanes 5-7 keep pads zero
        }
        if (l16 >= 8 && l16 < 13) {
            int d = l16 - 8;
            const float* r = sWr + d * 5;
            float w = fmaf(r[0], f0, fmaf(r[1], f1, fmaf(r[2], f2, fmaf(r[3], f3,
                      fmaf(r[4], f4, sb[d])))));
            sout[(size_t)i * 8 + d] = w;
        }
    } else { // POUT == 1: scalar p_next / self_next (stride 1)
        if (l16 == 0) {
            float w = fmaf(sWl[0], f0, fmaf(sWl[1], f1, fmaf(sWl[2], f2,
                      fmaf(sWl[3], f3, sWl[4] * f4))));
            pout[i] = w;
        }
        if (l16 == 1) {
            float w = fmaf(sWr[0], f0, fmaf(sWr[1], f1, fmaf(sWr[2], f2,
                      fmaf(sWr[3], f3, fmaf(sWr[4], f4, sb[0])))));
            sout[i] = w;
        }
    }
}

// ---------------- final scalar layer, two nodes per warp ----------------
__global__ void __launch_bounds__(256)
k_agg_final(const float* __restrict__ p, const float* __restrict__ self,
            float* __restrict__ out) {
    int t = threadIdx.x;
    int warp = t >> 5, lane = t & 31;
    int h = lane >> 4, l16 = lane & 15;
    int i = (blockIdx.x * (blockDim.x >> 5) + warp) * 2 + h;
    if (i - h >= N_NODES) return;

    int deg = g_cnt[i];
    int start = i << CAP_LOG, end = start + deg;
    float acc = 0.f;
    for (int j = start + l16; j < end; j += 16)
        acc += ldg_na1(p + __ldg(g_col + j));
    #pragma unroll
    for (int off = 1; off < 16; off <<= 1)
        acc += __shfl_xor_sync(FULL, acc, off);
    if (l16 == 0) {
        float inv = 1.0f / (float)max(deg, 1);
        out[i] = fmaf(acc, inv, __ldg(self + i));
    }
}

// ---------------- launch ----------------
extern "C" void kernel_launch(void* const* d_in, const int* in_sizes, int n_in,
                              void* d_out, int out_size) {
    const float* x    = (const float*)d_in[0];
    const int*   ei   = (const int*)  d_in[1];
    const float* Wl1  = (const float*)d_in[2];
    const float* Wr1  = (const float*)d_in[3];
    const float* b1   = (const float*)d_in[4];
    const float* Wlm  = (const float*)d_in[5];   // [8,5,5]
    const float* Wrm  = (const float*)d_in[6];   // [8,5,5]
    const float* bm   = (const float*)d_in[7];   // [8,5]
    const float* Wl10 = (const float*)d_in[8];   // [1,5]
    const float* Wr10 = (const float*)d_in[9];   // [1,5]
    const float* b10  = (const float*)d_in[10];  // [1]
    float* out = (float*)d_out;

    void *pa, *pb, *sa, *sb_, *pcnt;
    cudaGetSymbolAddress(&pa,   g_pa);
    cudaGetSymbolAddress(&pb,   g_pb);
    cudaGetSymbolAddress(&sa,   g_sa);
    cudaGetSymbolAddress(&sb_,  g_sb);
    cudaGetSymbolAddress(&pcnt, g_cnt);
    float* P[2] = { (float*)pa,  (float*)pb  };
    float* S[2] = { (float*)sa,  (float*)sb_ };

    const int E = N_EDGES;
    int e4blocks = (E / 4 + 255) / 256;      // fill blocks
    int nb       = (N_NODES + 255) / 256;    // proj blocks
    int npairs   = N_NODES / 2;
    int ablocks  = (npairs + 7) / 8;         // 2 nodes per warp, 8 warps/block

    cudaMemsetAsync(pcnt, 0, N_NODES * sizeof(int));
    k_build<<<e4blocks + nb, 256>>>(ei, E, e4blocks, x, Wl1, Wr1, b1, P[0], S[0]);

    // layers 0..7
    int cur = 0;
    for (int L = 0; L <= 7; ++L) {
        k_agg5<5><<<ablocks, 256>>>(P[cur], S[cur], P[1 - cur], S[1 - cur],
                                    Wlm + L * 25, Wrm + L * 25, bm + L * 5);
        cur = 1 - cur;
    }
    // layer 8: pre-project scalar p9/self9 with Wl10/Wr10/b10
    k_agg5<1><<<ablocks, 256>>>(P[cur], S[cur], P[1 - cur], S[1 - cur],
                                Wl10, Wr10, b10);
    cur = 1 - cur;
    // layer 9 (final, no relu): out = mean(p9) + self9
    k_agg_final<<<ablocks, 256>>>(P[cur], S[cur], out);
}

// round 14
// speedup vs baseline: 1.1141x; 1.1141x over previous
#include <cuda_runtime.h>

#define N_NODES 500000
#define N_EDGES 16000000
#define FULL 0xffffffffu
#define CAP_LOG 7                              // 128 slots per node bucket
#define CAP (1 << CAP_LOG)

// ---------------- device scratch (static; no allocation) ----------------
__device__ int   g_cnt[N_NODES];               // in-degree (also fill cursor)
__device__ int   g_col[(size_t)N_NODES * CAP]; // bucketized CSR: row i at i*CAP
__device__ float g_pa[(size_t)N_NODES * 8];    // projected features (32B records)
__device__ float g_pb[(size_t)N_NODES * 8];
__device__ float g_sa[(size_t)N_NODES * 8];    // precomputed self terms
__device__ float g_sb[(size_t)N_NODES * 8];

// ---------------- fused build: CSR fill (blocks [0,nfill)) + layer-0 proj (rest) ----------------
__global__ void __launch_bounds__(256)
k_build(const int* __restrict__ ei, int E, int nfill,
        const float* __restrict__ x,
        const float* __restrict__ Wl1, const float* __restrict__ Wr1,
        const float* __restrict__ b1,
        float* __restrict__ p0, float* __restrict__ s0) {
    if (blockIdx.x < nfill) {
        int e4 = (blockIdx.x * blockDim.x + threadIdx.x) * 4;
        if (e4 < E) {
            int4 d = *reinterpret_cast<const int4*>(ei + E + e4);  // dst
            int4 s = *reinterpret_cast<const int4*>(ei + e4);      // src
            int q0 = atomicAdd(&g_cnt[d.x], 1); g_col[((size_t)d.x << CAP_LOG) + q0] = s.x;
            int q1 = atomicAdd(&g_cnt[d.y], 1); g_col[((size_t)d.y << CAP_LOG) + q1] = s.y;
            int q2 = atomicAdd(&g_cnt[d.z], 1); g_col[((size_t)d.z << CAP_LOG) + q2] = s.z;
            int q3 = atomicAdd(&g_cnt[d.w], 1); g_col[((size_t)d.w << CAP_LOG) + q3] = s.w;
        }
        return;
    }
    // ---- layer-0 projection part ----
    __shared__ float sW[105];                 // Wl1(50) | Wr1(50) | b1(5)
    int t = threadIdx.x;
    if (t < 50)       sW[t] = Wl1[t];
    else if (t < 100) sW[t] = Wr1[t - 50];
    else if (t < 105) sW[t] = b1[t - 100];
    __syncthreads();

    int i = (blockIdx.x - nfill) * blockDim.x + t;
    if (i >= N_NODES) return;

    float xv[10];
    #pragma unroll
    for (int j = 0; j < 10; j++) xv[j] = x[(size_t)i * 10 + j];

    float pv[5], sv[5];
    #pragma unroll
    for (int d = 0; d < 5; d++) {
        float a = 0.f, bsum = sW[100 + d];
        #pragma unroll
        for (int j = 0; j < 10; j++) {
            a    = fmaf(sW[d * 10 + j],      xv[j], a);
            bsum = fmaf(sW[50 + d * 10 + j], xv[j], bsum);
        }
        pv[d] = a; sv[d] = bsum;
    }
    float4* pr = reinterpret_cast<float4*>(p0 + (size_t)i * 8);
    float4* sr = reinterpret_cast<float4*>(s0 + (size_t)i * 8);
    pr[0] = make_float4(pv[0], pv[1], pv[2], pv[3]);
    pr[1] = make_float4(pv[4], 0.f, 0.f, 0.f);
    sr[0] = make_float4(sv[0], sv[1], sv[2], sv[3]);
    sr[1] = make_float4(sv[4], 0.f, 0.f, 0.f);
}

// ---------------- fused 5-dim layer, TWO nodes per warp (round-10 proven) ----------------
// Gather at the L1tex replay floor: lane pairs load float4 halves of a node's
// 32B record (16 edges/LDG.128, 1 line/edge), 2x unrolled so 4 gather LDGs are
// in flight per warp. Reduce: fold halves (xor16), select node, 3 parity levels.
template<int POUT>
__global__ void __launch_bounds__(256)
k_agg5(const float* __restrict__ p, const float* __restrict__ self,
       float* __restrict__ pout, float* __restrict__ sout,
       const float* __restrict__ Wl, const float* __restrict__ Wr,
       const float* __restrict__ b) {
    __shared__ float sWl[POUT * 5], sWr[POUT * 5], sb[POUT];
    int t = threadIdx.x;
    if (t < POUT * 5)                 sWl[t]      = Wl[t];
    if (t >= 32 && t < 32 + POUT * 5) sWr[t - 32] = Wr[t - 32];
    if (t >= 64 && t < 64 + POUT)     sb[t - 64]  = b[t - 64];
    __syncthreads();

    int warp = t >> 5, lane = t & 31;
    int i0 = (blockIdx.x * (blockDim.x >> 5) + warp) * 2;
    if (i0 >= N_NODES) return;

    int2 dg = *reinterpret_cast<const int2*>(g_cnt + i0);   // degA, degB (i0 even)
    int degA = dg.x, degB = dg.y;
    int startA = i0 << CAP_LOG, startB = (i0 + 1) << CAP_LOG;
    int endA = startA + degA, endB = startB + degB;

    int half = lane & 1;                   // 0: p[0..3], 1: p[4..7]
    int epos = lane >> 1;                  // edge slot 0..15

    float4 accA = make_float4(0.f, 0.f, 0.f, 0.f);
    float4 accB = make_float4(0.f, 0.f, 0.f, 0.f);
    int jA = startA + epos, jB = startB + epos;
    while (jA < endA || jB < endB) {
        int sA0 = (jA      < endA) ? __ldg(g_col + jA)      : -1;
        int sA1 = (jA + 16 < endA) ? __ldg(g_col + jA + 16) : -1;
        int sB0 = (jB      < endB) ? __ldg(g_col + jB)      : -1;
        int sB1 = (jB + 16 < endB) ? __ldg(g_col + jB + 16) : -1;
        if (sA0 >= 0) {
            float4 v = __ldg(reinterpret_cast<const float4*>(p + (size_t)sA0 * 8) + half);
            accA.x += v.x; accA.y += v.y; accA.z += v.z; accA.w += v.w;
        }
        if (sB0 >= 0) {
            float4 v = __ldg(reinterpret_cast<const float4*>(p + (size_t)sB0 * 8) + half);
            accB.x += v.x; accB.y += v.y; accB.z += v.z; accB.w += v.w;
        }
        if (sA1 >= 0) {
            float4 v = __ldg(reinterpret_cast<const float4*>(p + (size_t)sA1 * 8) + half);
            accA.x += v.x; accA.y += v.y; accA.z += v.z; accA.w += v.w;
        }
        if (sB1 >= 0) {
            float4 v = __ldg(reinterpret_cast<const float4*>(p + (size_t)sB1 * 8) + half);
            accB.x += v.x; accB.y += v.y; accB.z += v.z; accB.w += v.w;
        }
        jA += 32; jB += 32;
    }

    int h    = lane >> 4;                  // which node this half-warp finishes
    int l16  = lane & 15;
    int base = lane & 16;
    int i    = i0 + h;
    int deg  = h ? degB : degA;

    // self load early: its latency hides under the shfl-reduction chain below
    float sv = (l16 < 5) ? __ldg(self + (size_t)i * 8 + l16) : 0.f;

    // fold across halves (xor 16 preserves lane parity)
    accA.x += __shfl_xor_sync(FULL, accA.x, 16);
    accA.y += __shfl_xor_sync(FULL, accA.y, 16);
    accA.z += __shfl_xor_sync(FULL, accA.z, 16);
    accA.w += __shfl_xor_sync(FULL, accA.w, 16);
    accB.x += __shfl_xor_sync(FULL, accB.x, 16);
    accB.y += __shfl_xor_sync(FULL, accB.y, 16);
    accB.z += __shfl_xor_sync(FULL, accB.z, 16);
    accB.w += __shfl_xor_sync(FULL, accB.w, 16);

    // select this half-warp's node, then 3 parity-preserving levels
    float4 u;
    u.x = h ? accB.x : accA.x;
    u.y = h ? accB.y : accA.y;
    u.z = h ? accB.z : accA.z;
    u.w = h ? accB.w : accA.w;
    #pragma unroll
    for (int off = 2; off <= 8; off <<= 1) {
        u.x += __shfl_xor_sync(FULL, u.x, off);
        u.y += __shfl_xor_sync(FULL, u.y, off);
        u.z += __shfl_xor_sync(FULL, u.z, off);
        u.w += __shfl_xor_sync(FULL, u.w, off);
    }

    float s0 = __shfl_sync(FULL, u.x, base);         // even lane: dims0-3
    float s1 = __shfl_sync(FULL, u.y, base);
    float s2 = __shfl_sync(FULL, u.z, base);
    float s3 = __shfl_sync(FULL, u.w, base);
    float s4 = __shfl_sync(FULL, u.x, base | 1);     // odd lane: dim4

    float inv = 1.0f / (float)max(deg, 1);

    float f0 = fmaxf(fmaf(s0, inv, __shfl_sync(FULL, sv, base + 0)), 0.f);
    float f1 = fmaxf(fmaf(s1, inv, __shfl_sync(FULL, sv, base + 1)), 0.f);
    float f2 = fmaxf(fmaf(s2, inv, __shfl_sync(FULL, sv, base + 2)), 0.f);
    float f3 = fmaxf(fmaf(s3, inv, __shfl_sync(FULL, sv, base + 3)), 0.f);
    float f4 = fmaxf(fmaf(s4, inv, __shfl_sync(FULL, sv, base + 4)), 0.f);

    if (POUT == 5) {
        if (l16 < 8) {
            float w = 0.f;
            if (l16 < 5) {
                const float* r = sWl + l16 * 5;
                w = fmaf(r[0], f0, fmaf(r[1], f1, fmaf(r[2], f2, fmaf(r[3], f3, r[4] * f4))));
            }
            pout[(size_t)i * 8 + l16] = w;   // lanes 5-7 keep pads zero
        }
        if (l16 >= 8 && l16 < 13) {
            int d = l16 - 8;
            const float* r = sWr + d * 5;
            float w = fmaf(r[0], f0, fmaf(r[1], f1, fmaf(r[2], f2, fmaf(r[3], f3,
                      fmaf(r[4], f4, sb[d])))));
            sout[(size_t)i * 8 + d] = w;
        }
    } else { // POUT == 1: scalar p_next / self_next (stride 1)
        if (l16 == 0) {
            float w = fmaf(sWl[0], f0, fmaf(sWl[1], f1, fmaf(sWl[2], f2,
                      fmaf(sWl[3], f3, sWl[4] * f4))));
            pout[i] = w;
        }
        if (l16 == 1) {
            float w = fmaf(sWr[0], f0, fmaf(sWr[1], f1, fmaf(sWr[2], f2,
                      fmaf(sWr[3], f3, fmaf(sWr[4], f4, sb[0])))));
            sout[i] = w;
        }
    }
}

// ---------------- final scalar layer, two nodes per warp, 2x unrolled ----------------
__global__ void __launch_bounds__(256)
k_agg_final(const float* __restrict__ p, const float* __restrict__ self,
            float* __restrict__ out) {
    int t = threadIdx.x;
    int warp = t >> 5, lane = t & 31;
    int h = lane >> 4, l16 = lane & 15;
    int i = (blockIdx.x * (blockDim.x >> 5) + warp) * 2 + h;
    if (i - h >= N_NODES) return;

    int deg = g_cnt[i];
    int start = i << CAP_LOG, end = start + deg;
    float acc = 0.f;
    int j = start + l16;
    while (j < end) {
        int c0 = __ldg(g_col + j);
        int c1 = (j + 16 < end) ? __ldg(g_col + j + 16) : -1;
        acc += __ldg(p + c0);
        if (c1 >= 0) acc += __ldg(p + c1);
        j += 32;
    }
    #pragma unroll
    for (int off = 1; off < 16; off <<= 1)
        acc += __shfl_xor_sync(FULL, acc, off);
    if (l16 == 0) {
        float inv = 1.0f / (float)max(deg, 1);
        out[i] = fmaf(acc, inv, __ldg(self + i));
    }
}

// ---------------- launch ----------------
extern "C" void kernel_launch(void* const* d_in, const int* in_sizes, int n_in,
                              void* d_out, int out_size) {
    const float* x    = (const float*)d_in[0];
    const int*   ei   = (const int*)  d_in[1];
    const float* Wl1  = (const float*)d_in[2];
    const float* Wr1  = (const float*)d_in[3];
    const float* b1   = (const float*)d_in[4];
    const float* Wlm  = (const float*)d_in[5];   // [8,5,5]
    const float* Wrm  = (const float*)d_in[6];   // [8,5,5]
    const float* bm   = (const float*)d_in[7];   // [8,5]
    const float* Wl10 = (const float*)d_in[8];   // [1,5]
    const float* Wr10 = (const float*)d_in[9];   // [1,5]
    const float* b10  = (const float*)d_in[10];  // [1]
    float* out = (float*)d_out;

    void *pa, *pb, *sa, *sb_, *pcnt;
    cudaGetSymbolAddress(&pa,   g_pa);
    cudaGetSymbolAddress(&pb,   g_pb);
    cudaGetSymbolAddress(&sa,   g_sa);
    cudaGetSymbolAddress(&sb_,  g_sb);
    cudaGetSymbolAddress(&pcnt, g_cnt);
    float* P[2] = { (float*)pa,  (float*)pb  };
    float* S[2] = { (float*)sa,  (float*)sb_ };

    const int E = N_EDGES;
    int e4blocks = (E / 4 + 255) / 256;      // fill blocks
    int nb       = (N_NODES + 255) / 256;    // proj blocks
    int npairs   = N_NODES / 2;
    int ablocks  = (npairs + 7) / 8;         // 2 nodes per warp, 8 warps/block

    cudaMemsetAsync(pcnt, 0, N_NODES * sizeof(int));
    k_build<<<e4blocks + nb, 256>>>(ei, E, e4blocks, x, Wl1, Wr1, b1, P[0], S[0]);

    // layers 0..7
    int cur = 0;
    for (int L = 0; L <= 7; ++L) {
        k_agg5<5><<<ablocks, 256>>>(P[cur], S[cur], P[1 - cur], S[1 - cur],
                                    Wlm + L * 25, Wrm + L * 25, bm + L * 5);
        cur = 1 - cur;
    }
    // layer 8: pre-project scalar p9/self9 with Wl10/Wr10/b10
    k_agg5<1><<<ablocks, 256>>>(P[cur], S[cur], P[1 - cur], S[1 - cur],
                                Wl10, Wr10, b10);
    cur = 1 - cur;
    // layer 9 (final, no relu): out = mean(p9) + self9
    k_agg_final<<<ablocks, 256>>>(P[cur], S[cur], out);
}

// round 15
// speedup vs baseline: 1.1252x; 1.0100x over previous
#include <cuda_runtime.h>

#define N_NODES 500000
#define N_EDGES 16000000
#define FULL 0xffffffffu
#define CAP_LOG 7                              // 128 slots per node bucket
#define CAP (1 << CAP_LOG)

// ---------------- device scratch (static; no allocation) ----------------
__device__ int   g_cnt[N_NODES];               // in-degree (also fill cursor)
__device__ int   g_col[(size_t)N_NODES * CAP]; // bucketized CSR: row i at i*CAP
__device__ float g_pa[(size_t)N_NODES * 8];    // projected features (32B records)
__device__ float g_pb[(size_t)N_NODES * 8];
__device__ float g_sa[(size_t)N_NODES * 8];    // precomputed self terms
__device__ float g_sb[(size_t)N_NODES * 8];

// PDL device controls. griddepcontrol.wait is a no-op when the kernel was
// launched without a programmatic dependency -> safe in the fallback path.
__device__ __forceinline__ void gdc_wait() {
    asm volatile("griddepcontrol.wait;" ::: "memory");
}
__device__ __forceinline__ void gdc_launch_dependents() {
    asm volatile("griddepcontrol.launch_dependents;" ::: "memory");
}

// ---------------- fused build: CSR fill (blocks [0,nfill)) + layer-0 proj (rest) ----------------
__global__ void __launch_bounds__(256)
k_build(const int* __restrict__ ei, int E, int nfill,
        const float* __restrict__ x,
        const float* __restrict__ Wl1, const float* __restrict__ Wr1,
        const float* __restrict__ b1,
        float* __restrict__ p0, float* __restrict__ s0) {
    if (blockIdx.x < nfill) {
        int e4 = (blockIdx.x * blockDim.x + threadIdx.x) * 4;
        if (e4 < E) {
            int4 d = *reinterpret_cast<const int4*>(ei + E + e4);  // dst
            int4 s = *reinterpret_cast<const int4*>(ei + e4);      // src
            int q0 = atomicAdd(&g_cnt[d.x], 1); g_col[((size_t)d.x << CAP_LOG) + q0] = s.x;
            int q1 = atomicAdd(&g_cnt[d.y], 1); g_col[((size_t)d.y << CAP_LOG) + q1] = s.y;
            int q2 = atomicAdd(&g_cnt[d.z], 1); g_col[((size_t)d.z << CAP_LOG) + q2] = s.z;
            int q3 = atomicAdd(&g_cnt[d.w], 1); g_col[((size_t)d.w << CAP_LOG) + q3] = s.w;
        }
        gdc_launch_dependents();
        return;
    }
    // ---- layer-0 projection part ----
    __shared__ float sW[105];                 // Wl1(50) | Wr1(50) | b1(5)
    int t = threadIdx.x;
    if (t < 50)       sW[t] = Wl1[t];
    else if (t < 100) sW[t] = Wr1[t - 50];
    else if (t < 105) sW[t] = b1[t - 100];
    __syncthreads();

    int i = (blockIdx.x - nfill) * blockDim.x + t;
    if (i >= N_NODES) { gdc_launch_dependents(); return; }

    float xv[10];
    #pragma unroll
    for (int j = 0; j < 10; j++) xv[j] = x[(size_t)i * 10 + j];

    float pv[5], sv[5];
    #pragma unroll
    for (int d = 0; d < 5; d++) {
        float a = 0.f, bsum = sW[100 + d];
        #pragma unroll
        for (int j = 0; j < 10; j++) {
            a    = fmaf(sW[d * 10 + j],      xv[j], a);
            bsum = fmaf(sW[50 + d * 10 + j], xv[j], bsum);
        }
        pv[d] = a; sv[d] = bsum;
    }
    float4* pr = reinterpret_cast<float4*>(p0 + (size_t)i * 8);
    float4* sr = reinterpret_cast<float4*>(s0 + (size_t)i * 8);
    pr[0] = make_float4(pv[0], pv[1], pv[2], pv[3]);
    pr[1] = make_float4(pv[4], 0.f, 0.f, 0.f);
    sr[0] = make_float4(sv[0], sv[1], sv[2], sv[3]);
    sr[1] = make_float4(sv[4], 0.f, 0.f, 0.f);
    gdc_launch_dependents();
}

// ---------------- fused 5-dim layer, TWO nodes per warp (round-10 proven) ----------------
// Gather at the L1tex replay floor: lane pairs load float4 halves of a node's
// 32B record (16 edges/LDG.128, 1 line/edge), 2x unrolled so 4 gather LDGs are
// in flight per warp. LATEWAIT: CSR metadata (immutable after build) is read
// BEFORE griddepcontrol.wait so it overlaps the previous layer's tail.
template<int POUT, bool LATEWAIT>
__global__ void __launch_bounds__(256)
k_agg5(const float* __restrict__ p, const float* __restrict__ self,
       float* __restrict__ pout, float* __restrict__ sout,
       const float* __restrict__ Wl, const float* __restrict__ Wr,
       const float* __restrict__ b) {
    __shared__ float sWl[POUT * 5], sWr[POUT * 5], sb[POUT];
    int t = threadIdx.x;
    if (t < POUT * 5)                 sWl[t]      = Wl[t];
    if (t >= 32 && t < 32 + POUT * 5) sWr[t - 32] = Wr[t - 32];
    if (t >= 64 && t < 64 + POUT)     sb[t - 64]  = b[t - 64];
    __syncthreads();

    int warp = t >> 5, lane = t & 31;
    int i0 = (blockIdx.x * (blockDim.x >> 5) + warp) * 2;
    if (i0 >= N_NODES) { gdc_wait(); gdc_launch_dependents(); return; }

    if (!LATEWAIT) gdc_wait();            // layer 0: CSR itself is dependent

    int2 dg = *reinterpret_cast<const int2*>(g_cnt + i0);   // degA, degB (i0 even)
    int degA = dg.x, degB = dg.y;
    int startA = i0 << CAP_LOG, startB = (i0 + 1) << CAP_LOG;
    int endA = startA + degA, endB = startB + degB;

    int half = lane & 1;                   // 0: p[0..3], 1: p[4..7]
    int epos = lane >> 1;                  // edge slot 0..15

    if (LATEWAIT) gdc_wait();             // p/self become safe to read here

    float4 accA = make_float4(0.f, 0.f, 0.f, 0.f);
    float4 accB = make_float4(0.f, 0.f, 0.f, 0.f);
    int jA = startA + epos, jB = startB + epos;
    while (jA < endA || jB < endB) {
        int sA0 = (jA      < endA) ? __ldg(g_col + jA)      : -1;
        int sA1 = (jA + 16 < endA) ? __ldg(g_col + jA + 16) : -1;
        int sB0 = (jB      < endB) ? __ldg(g_col + jB)      : -1;
        int sB1 = (jB + 16 < endB) ? __ldg(g_col + jB + 16) : -1;
        if (sA0 >= 0) {
            float4 v = __ldg(reinterpret_cast<const float4*>(p + (size_t)sA0 * 8) + half);
            accA.x += v.x; accA.y += v.y; accA.z += v.z; accA.w += v.w;
        }
        if (sB0 >= 0) {
            float4 v = __ldg(reinterpret_cast<const float4*>(p + (size_t)sB0 * 8) + half);
            accB.x += v.x; accB.y += v.y; accB.z += v.z; accB.w += v.w;
        }
        if (sA1 >= 0) {
            float4 v = __ldg(reinterpret_cast<const float4*>(p + (size_t)sA1 * 8) + half);
            accA.x += v.x; accA.y += v.y; accA.z += v.z; accA.w += v.w;
        }
        if (sB1 >= 0) {
            float4 v = __ldg(reinterpret_cast<const float4*>(p + (size_t)sB1 * 8) + half);
            accB.x += v.x; accB.y += v.y; accB.z += v.z; accB.w += v.w;
        }
        jA += 32; jB += 32;
    }

    int h    = lane >> 4;                  // which node this half-warp finishes
    int l16  = lane & 15;
    int base = lane & 16;
    int i    = i0 + h;
    int deg  = h ? degB : degA;

    // self load early: its latency hides under the shfl-reduction chain below
    float sv = (l16 < 5) ? __ldg(self + (size_t)i * 8 + l16) : 0.f;

    // fold across halves (xor 16 preserves lane parity)
    accA.x += __shfl_xor_sync(FULL, accA.x, 16);
    accA.y += __shfl_xor_sync(FULL, accA.y, 16);
    accA.z += __shfl_xor_sync(FULL, accA.z, 16);
    accA.w += __shfl_xor_sync(FULL, accA.w, 16);
    accB.x += __shfl_xor_sync(FULL, accB.x, 16);
    accB.y += __shfl_xor_sync(FULL, accB.y, 16);
    accB.z += __shfl_xor_sync(FULL, accB.z, 16);
    accB.w += __shfl_xor_sync(FULL, accB.w, 16);

    // select this half-warp's node, then 3 parity-preserving levels
    float4 u;
    u.x = h ? accB.x : accA.x;
    u.y = h ? accB.y : accA.y;
    u.z = h ? accB.z : accA.z;
    u.w = h ? accB.w : accA.w;
    #pragma unroll
    for (int off = 2; off <= 8; off <<= 1) {
        u.x += __shfl_xor_sync(FULL, u.x, off);
        u.y += __shfl_xor_sync(FULL, u.y, off);
        u.z += __shfl_xor_sync(FULL, u.z, off);
        u.w += __shfl_xor_sync(FULL, u.w, off);
    }

    float s0 = __shfl_sync(FULL, u.x, base);         // even lane: dims0-3
    float s1 = __shfl_sync(FULL, u.y, base);
    float s2 = __shfl_sync(FULL, u.z, base);
    float s3 = __shfl_sync(FULL, u.w, base);
    float s4 = __shfl_sync(FULL, u.x, base | 1);     // odd lane: dim4

    float inv = 1.0f / (float)max(deg, 1);

    float f0 = fmaxf(fmaf(s0, inv, __shfl_sync(FULL, sv, base + 0)), 0.f);
    float f1 = fmaxf(fmaf(s1, inv, __shfl_sync(FULL, sv, base + 1)), 0.f);
    float f2 = fmaxf(fmaf(s2, inv, __shfl_sync(FULL, sv, base + 2)), 0.f);
    float f3 = fmaxf(fmaf(s3, inv, __shfl_sync(FULL, sv, base + 3)), 0.f);
    float f4 = fmaxf(fmaf(s4, inv, __shfl_sync(FULL, sv, base + 4)), 0.f);

    if (POUT == 5) {
        if (l16 < 8) {
            float w = 0.f;
            if (l16 < 5) {
                const float* r = sWl + l16 * 5;
                w = fmaf(r[0], f0, fmaf(r[1], f1, fmaf(r[2], f2, fmaf(r[3], f3, r[4] * f4))));
            }
            pout[(size_t)i * 8 + l16] = w;   // lanes 5-7 keep pads zero
        }
        if (l16 >= 8 && l16 < 13) {
            int d = l16 - 8;
            const float* r = sWr + d * 5;
            float w = fmaf(r[0], f0, fmaf(r[1], f1, fmaf(r[2], f2, fmaf(r[3], f3,
                      fmaf(r[4], f4, sb[d])))));
            sout[(size_t)i * 8 + d] = w;
        }
    } else { // POUT == 1: scalar p_next / self_next (stride 1)
        if (l16 == 0) {
            float w = fmaf(sWl[0], f0, fmaf(sWl[1], f1, fmaf(sWl[2], f2,
                      fmaf(sWl[3], f3, sWl[4] * f4))));
            pout[i] = w;
        }
        if (l16 == 1) {
            float w = fmaf(sWr[0], f0, fmaf(sWr[1], f1, fmaf(sWr[2], f2,
                      fmaf(sWr[3], f3, fmaf(sWr[4], f4, sb[0])))));
            sout[i] = w;
        }
    }
    gdc_launch_dependents();               // stores above are visible to waiters
}

// ---------------- final scalar layer, two nodes per warp, 2x unrolled ----------------
__global__ void __launch_bounds__(256)
k_agg_final(const float* __restrict__ p, const float* __restrict__ self,
            float* __restrict__ out) {
    int t = threadIdx.x;
    int warp = t >> 5, lane = t & 31;
    int h = lane >> 4, l16 = lane & 15;
    int i = (blockIdx.x * (blockDim.x >> 5) + warp) * 2 + h;
    if (i - h >= N_NODES) { gdc_wait(); return; }

    int deg = g_cnt[i];                    // CSR metadata: pre-wait
    int start = i << CAP_LOG, end = start + deg;

    gdc_wait();                            // p9/self9 safe from here

    float acc = 0.f;
    int j = start + l16;
    while (j < end) {
        int c0 = __ldg(g_col + j);
        int c1 = (j + 16 < end) ? __ldg(g_col + j + 16) : -1;
        acc += __ldg(p + c0);
        if (c1 >= 0) acc += __ldg(p + c1);
        j += 32;
    }
    #pragma unroll
    for (int off = 1; off < 16; off <<= 1)
        acc += __shfl_xor_sync(FULL, acc, off);
    if (l16 == 0) {
        float inv = 1.0f / (float)max(deg, 1);
        out[i] = fmaf(acc, inv, __ldg(self + i));
    }
}

// ---------------- host: launch with PDL attribute, fallback to plain ----------------
template<typename K, typename... Args>
static inline void launch_pdl(K kern, int grid, Args... args) {
    cudaLaunchAttribute attr[1];
    attr[0].id = cudaLaunchAttributeProgrammaticStreamSerialization;
    attr[0].val.programmaticStreamSerializationAllowed = 1;
    cudaLaunchConfig_t cfg{};
    cfg.gridDim  = dim3(grid);
    cfg.blockDim = dim3(256);
    cfg.dynamicSmemBytes = 0;
    cfg.stream   = 0;
    cfg.attrs    = attr;
    cfg.numAttrs = 1;
    if (cudaLaunchKernelEx(&cfg, kern, args...) != cudaSuccess) {
        kern<<<grid, 256>>>(args...);      // fallback: wait() degrades to no-op
    }
}

// ---------------- launch ----------------
extern "C" void kernel_launch(void* const* d_in, const int* in_sizes, int n_in,
                              void* d_out, int out_size) {
    const float* x    = (const float*)d_in[0];
    const int*   ei   = (const int*)  d_in[1];
    const float* Wl1  = (const float*)d_in[2];
    const float* Wr1  = (const float*)d_in[3];
    const float* b1   = (const float*)d_in[4];
    const float* Wlm  = (const float*)d_in[5];   // [8,5,5]
    const float* Wrm  = (const float*)d_in[6];   // [8,5,5]
    const float* bm   = (const float*)d_in[7];   // [8,5]
    const float* Wl10 = (const float*)d_in[8];   // [1,5]
    const float* Wr10 = (const float*)d_in[9];   // [1,5]
    const float* b10  = (const float*)d_in[10];  // [1]
    float* out = (float*)d_out;

    void *pa, *pb, *sa, *sb_, *pcnt;
    cudaGetSymbolAddress(&pa,   g_pa);
    cudaGetSymbolAddress(&pb,   g_pb);
    cudaGetSymbolAddress(&sa,   g_sa);
    cudaGetSymbolAddress(&sb_,  g_sb);
    cudaGetSymbolAddress(&pcnt, g_cnt);
    float* P[2] = { (float*)pa,  (float*)pb  };
    float* S[2] = { (float*)sa,  (float*)sb_ };

    const int E = N_EDGES;
    int e4blocks = (E / 4 + 255) / 256;      // fill blocks
    int nb       = (N_NODES + 255) / 256;    // proj blocks
    int npairs   = N_NODES / 2;
    int ablocks  = (npairs + 7) / 8;         // 2 nodes per warp, 8 warps/block

    cudaMemsetAsync(pcnt, 0, N_NODES * sizeof(int));
    k_build<<<e4blocks + nb, 256>>>(ei, E, e4blocks, x, Wl1, Wr1, b1, P[0], S[0]);

    // layer 0: CSR is dependent -> early wait variant
    launch_pdl(k_agg5<5, false>, ablocks,
               (const float*)P[0], (const float*)S[0], P[1], S[1],
               Wlm + 0 * 25, Wrm + 0 * 25, bm + 0 * 5);
    int cur = 1;
    // layers 1..7: CSR immutable -> late wait (prologue overlaps prev tail)
    for (int L = 1; L <= 7; ++L) {
        launch_pdl(k_agg5<5, true>, ablocks,
                   (const float*)P[cur], (const float*)S[cur], P[1 - cur], S[1 - cur],
                   Wlm + L * 25, Wrm + L * 25, bm + L * 5);
        cur = 1 - cur;
    }
    // layer 8: pre-project scalar p9/self9 with Wl10/Wr10/b10
    launch_pdl(k_agg5<1, true>, ablocks,
               (const float*)P[cur], (const float*)S[cur], P[1 - cur], S[1 - cur],
               Wl10, Wr10, b10);
    cur = 1 - cur;
    // layer 9 (final, no relu): out = mean(p9) + self9
    launch_pdl(k_agg_final, ablocks,
               (const float*)P[cur], (const float*)S[cur], out);
}

// round 16
// speedup vs baseline: 1.1483x; 1.0205x over previous
#include <cuda_runtime.h>

#define N_NODES 500000
#define N_EDGES 16000000
#define FULL 0xffffffffu
#define CAP_LOG 7                              // 128 slots per node bucket
#define CAP (1 << CAP_LOG)

// ---------------- device scratch (static; no allocation) ----------------
__device__ int   g_cnt[N_NODES];               // in-degree (also fill cursor)
__device__ int   g_col[(size_t)N_NODES * CAP]; // bucketized CSR: row i at i*CAP
__device__ float g_pa[(size_t)N_NODES * 8];    // projected features (32B records)
__device__ float g_pb[(size_t)N_NODES * 8];
__device__ float g_sa[(size_t)N_NODES * 8];    // precomputed self terms
__device__ float g_sb[(size_t)N_NODES * 8];

// PDL device controls. griddepcontrol.wait is a no-op when the kernel was
// launched without a programmatic dependency -> safe in the fallback path.
__device__ __forceinline__ void gdc_wait() {
    asm volatile("griddepcontrol.wait;" ::: "memory");
}
__device__ __forceinline__ void gdc_launch_dependents() {
    asm volatile("griddepcontrol.launch_dependents;" ::: "memory");
}

// ---------------- fused build: CSR fill (blocks [0,nfill)) + layer-0 proj (rest) ----------------
__global__ void __launch_bounds__(256)
k_build(const int* __restrict__ ei, int E, int nfill,
        const float* __restrict__ x,
        const float* __restrict__ Wl1, const float* __restrict__ Wr1,
        const float* __restrict__ b1,
        float* __restrict__ p0, float* __restrict__ s0) {
    if (blockIdx.x < nfill) {
        int e4 = (blockIdx.x * blockDim.x + threadIdx.x) * 4;
        if (e4 < E) {
            int4 d = *reinterpret_cast<const int4*>(ei + E + e4);  // dst
            int4 s = *reinterpret_cast<const int4*>(ei + e4);      // src
            int q0 = atomicAdd(&g_cnt[d.x], 1); g_col[((size_t)d.x << CAP_LOG) + q0] = s.x;
            int q1 = atomicAdd(&g_cnt[d.y], 1); g_col[((size_t)d.y << CAP_LOG) + q1] = s.y;
            int q2 = atomicAdd(&g_cnt[d.z], 1); g_col[((size_t)d.z << CAP_LOG) + q2] = s.z;
            int q3 = atomicAdd(&g_cnt[d.w], 1); g_col[((size_t)d.w << CAP_LOG) + q3] = s.w;
        }
        gdc_launch_dependents();
        return;
    }
    // ---- layer-0 projection part ----
    __shared__ float sW[105];                 // Wl1(50) | Wr1(50) | b1(5)
    int t = threadIdx.x;
    if (t < 50)       sW[t] = Wl1[t];
    else if (t < 100) sW[t] = Wr1[t - 50];
    else if (t < 105) sW[t] = b1[t - 100];
    __syncthreads();

    int i = (blockIdx.x - nfill) * blockDim.x + t;
    if (i >= N_NODES) { gdc_launch_dependents(); return; }

    float xv[10];
    #pragma unroll
    for (int j = 0; j < 10; j++) xv[j] = x[(size_t)i * 10 + j];

    float pv[5], sv[5];
    #pragma unroll
    for (int d = 0; d < 5; d++) {
        float a = 0.f, bsum = sW[100 + d];
        #pragma unroll
        for (int j = 0; j < 10; j++) {
            a    = fmaf(sW[d * 10 + j],      xv[j], a);
            bsum = fmaf(sW[50 + d * 10 + j], xv[j], bsum);
        }
        pv[d] = a; sv[d] = bsum;
    }
    float4* pr = reinterpret_cast<float4*>(p0 + (size_t)i * 8);
    float4* sr = reinterpret_cast<float4*>(s0 + (size_t)i * 8);
    pr[0] = make_float4(pv[0], pv[1], pv[2], pv[3]);
    pr[1] = make_float4(pv[4], 0.f, 0.f, 0.f);
    sr[0] = make_float4(sv[0], sv[1], sv[2], sv[3]);
    sr[1] = make_float4(sv[4], 0.f, 0.f, 0.f);
    gdc_launch_dependents();
}

// ---------------- fused 5-dim layer, TWO nodes per warp, 128-thread blocks ----------------
// Gather at the L1tex replay floor: lane pairs load float4 halves of a node's
// 32B record (16 edges/LDG.128, 1 line/edge), 2x unrolled so 4 gather LDGs are
// in flight per warp. 4-warp blocks: finer SM scheduling quanta -> higher
// sustained eligible-warp count. LATEWAIT: CSR metadata read before gdc_wait.
template<int POUT, bool LATEWAIT>
__global__ void __launch_bounds__(128)
k_agg5(const float* __restrict__ p, const float* __restrict__ self,
       float* __restrict__ pout, float* __restrict__ sout,
       const float* __restrict__ Wl, const float* __restrict__ Wr,
       const float* __restrict__ b) {
    __shared__ float sWl[POUT * 5], sWr[POUT * 5], sb[POUT];
    int t = threadIdx.x;
    if (t < POUT * 5)                 sWl[t]      = Wl[t];
    if (t >= 32 && t < 32 + POUT * 5) sWr[t - 32] = Wr[t - 32];
    if (t >= 64 && t < 64 + POUT)     sb[t - 64]  = b[t - 64];
    __syncthreads();

    int warp = t >> 5, lane = t & 31;
    int i0 = (blockIdx.x * (blockDim.x >> 5) + warp) * 2;
    if (i0 >= N_NODES) { gdc_wait(); gdc_launch_dependents(); return; }

    if (!LATEWAIT) gdc_wait();            // layer 0: CSR itself is dependent

    int2 dg = *reinterpret_cast<const int2*>(g_cnt + i0);   // degA, degB (i0 even)
    int degA = dg.x, degB = dg.y;
    int startA = i0 << CAP_LOG, startB = (i0 + 1) << CAP_LOG;
    int endA = startA + degA, endB = startB + degB;

    int half = lane & 1;                   // 0: p[0..3], 1: p[4..7]
    int epos = lane >> 1;                  // edge slot 0..15

    if (LATEWAIT) gdc_wait();             // p/self become safe to read here

    float4 accA = make_float4(0.f, 0.f, 0.f, 0.f);
    float4 accB = make_float4(0.f, 0.f, 0.f, 0.f);
    int jA = startA + epos, jB = startB + epos;
    while (jA < endA || jB < endB) {
        int sA0 = (jA      < endA) ? __ldg(g_col + jA)      : -1;
        int sA1 = (jA + 16 < endA) ? __ldg(g_col + jA + 16) : -1;
        int sB0 = (jB      < endB) ? __ldg(g_col + jB)      : -1;
        int sB1 = (jB + 16 < endB) ? __ldg(g_col + jB + 16) : -1;
        if (sA0 >= 0) {
            float4 v = __ldg(reinterpret_cast<const float4*>(p + (size_t)sA0 * 8) + half);
            accA.x += v.x; accA.y += v.y; accA.z += v.z; accA.w += v.w;
        }
        if (sB0 >= 0) {
            float4 v = __ldg(reinterpret_cast<const float4*>(p + (size_t)sB0 * 8) + half);
            accB.x += v.x; accB.y += v.y; accB.z += v.z; accB.w += v.w;
        }
        if (sA1 >= 0) {
            float4 v = __ldg(reinterpret_cast<const float4*>(p + (size_t)sA1 * 8) + half);
            accA.x += v.x; accA.y += v.y; accA.z += v.z; accA.w += v.w;
        }
        if (sB1 >= 0) {
            float4 v = __ldg(reinterpret_cast<const float4*>(p + (size_t)sB1 * 8) + half);
            accB.x += v.x; accB.y += v.y; accB.z += v.z; accB.w += v.w;
        }
        jA += 32; jB += 32;
    }

    int h    = lane >> 4;                  // which node this half-warp finishes
    int l16  = lane & 15;
    int base = lane & 16;
    int i    = i0 + h;
    int deg  = h ? degB : degA;

    // self load early: its latency hides under the shfl-reduction chain below
    float sv = (l16 < 5) ? __ldg(self + (size_t)i * 8 + l16) : 0.f;

    // fold across halves (xor 16 preserves lane parity)
    accA.x += __shfl_xor_sync(FULL, accA.x, 16);
    accA.y += __shfl_xor_sync(FULL, accA.y, 16);
    accA.z += __shfl_xor_sync(FULL, accA.z, 16);
    accA.w += __shfl_xor_sync(FULL, accA.w, 16);
    accB.x += __shfl_xor_sync(FULL, accB.x, 16);
    accB.y += __shfl_xor_sync(FULL, accB.y, 16);
    accB.z += __shfl_xor_sync(FULL, accB.z, 16);
    accB.w += __shfl_xor_sync(FULL, accB.w, 16);

    // select this half-warp's node, then 3 parity-preserving levels
    float4 u;
    u.x = h ? accB.x : accA.x;
    u.y = h ? accB.y : accA.y;
    u.z = h ? accB.z : accA.z;
    u.w = h ? accB.w : accA.w;
    #pragma unroll
    for (int off = 2; off <= 8; off <<= 1) {
        u.x += __shfl_xor_sync(FULL, u.x, off);
        u.y += __shfl_xor_sync(FULL, u.y, off);
        u.z += __shfl_xor_sync(FULL, u.z, off);
        u.w += __shfl_xor_sync(FULL, u.w, off);
    }

    float s0 = __shfl_sync(FULL, u.x, base);         // even lane: dims0-3
    float s1 = __shfl_sync(FULL, u.y, base);
    float s2 = __shfl_sync(FULL, u.z, base);
    float s3 = __shfl_sync(FULL, u.w, base);
    float s4 = __shfl_sync(FULL, u.x, base | 1);     // odd lane: dim4

    float inv = 1.0f / (float)max(deg, 1);

    float f0 = fmaxf(fmaf(s0, inv, __shfl_sync(FULL, sv, base + 0)), 0.f);
    float f1 = fmaxf(fmaf(s1, inv, __shfl_sync(FULL, sv, base + 1)), 0.f);
    float f2 = fmaxf(fmaf(s2, inv, __shfl_sync(FULL, sv, base + 2)), 0.f);
    float f3 = fmaxf(fmaf(s3, inv, __shfl_sync(FULL, sv, base + 3)), 0.f);
    float f4 = fmaxf(fmaf(s4, inv, __shfl_sync(FULL, sv, base + 4)), 0.f);

    if (POUT == 5) {
        if (l16 < 8) {
            float w = 0.f;
            if (l16 < 5) {
                const float* r = sWl + l16 * 5;
                w = fmaf(r[0], f0, fmaf(r[1], f1, fmaf(r[2], f2, fmaf(r[3], f3, r[4] * f4))));
            }
            pout[(size_t)i * 8 + l16] = w;   // lanes 5-7 keep pads zero
        }
        if (l16 >= 8 && l16 < 13) {
            int d = l16 - 8;
            const float* r = sWr + d * 5;
            float w = fmaf(r[0], f0, fmaf(r[1], f1, fmaf(r[2], f2, fmaf(r[3], f3,
                      fmaf(r[4], f4, sb[d])))));
            sout[(size_t)i * 8 + d] = w;
        }
    } else { // POUT == 1: scalar p_next / self_next (stride 1)
        if (l16 == 0) {
            float w = fmaf(sWl[0], f0, fmaf(sWl[1], f1, fmaf(sWl[2], f2,
                      fmaf(sWl[3], f3, sWl[4] * f4))));
            pout[i] = w;
        }
        if (l16 == 1) {
            float w = fmaf(sWr[0], f0, fmaf(sWr[1], f1, fmaf(sWr[2], f2,
                      fmaf(sWr[3], f3, fmaf(sWr[4], f4, sb[0])))));
            sout[i] = w;
        }
    }
    gdc_launch_dependents();               // stores above are visible to waiters
}

// ---------------- final scalar layer, two nodes per warp, 128-thread blocks ----------------
__global__ void __launch_bounds__(128)
k_agg_final(const float* __restrict__ p, const float* __restrict__ self,
            float* __restrict__ out) {
    int t = threadIdx.x;
    int warp = t >> 5, lane = t & 31;
    int h = lane >> 4, l16 = lane & 15;
    int i = (blockIdx.x * (blockDim.x >> 5) + warp) * 2 + h;
    if (i - h >= N_NODES) { gdc_wait(); return; }

    int deg = g_cnt[i];                    // CSR metadata: pre-wait
    int start = i << CAP_LOG, end = start + deg;

    gdc_wait();                            // p9/self9 safe from here

    float acc = 0.f;
    int j = start + l16;
    while (j < end) {
        int c0 = __ldg(g_col + j);
        int c1 = (j + 16 < end) ? __ldg(g_col + j + 16) : -1;
        acc += __ldg(p + c0);
        if (c1 >= 0) acc += __ldg(p + c1);
        j += 32;
    }
    #pragma unroll
    for (int off = 1; off < 16; off <<= 1)
        acc += __shfl_xor_sync(FULL, acc, off);
    if (l16 == 0) {
        float inv = 1.0f / (float)max(deg, 1);
        out[i] = fmaf(acc, inv, __ldg(self + i));
    }
}

// ---------------- host: launch with PDL attribute, fallback to plain ----------------
template<typename K, typename... Args>
static inline void launch_pdl(K kern, int grid, int block, Args... args) {
    cudaLaunchAttribute attr[1];
    attr[0].id = cudaLaunchAttributeProgrammaticStreamSerialization;
    attr[0].val.programmaticStreamSerializationAllowed = 1;
    cudaLaunchConfig_t cfg{};
    cfg.gridDim  = dim3(grid);
    cfg.blockDim = dim3(block);
    cfg.dynamicSmemBytes = 0;
    cfg.stream   = 0;
    cfg.attrs    = attr;
    cfg.numAttrs = 1;
    if (cudaLaunchKernelEx(&cfg, kern, args...) != cudaSuccess) {
        kern<<<grid, block>>>(args...);    // fallback: wait() degrades to no-op
    }
}

// ---------------- launch ----------------
extern "C" void kernel_launch(void* const* d_in, const int* in_sizes, int n_in,
                              void* d_out, int out_size) {
    const float* x    = (const float*)d_in[0];
    const int*   ei   = (const int*)  d_in[1];
    const float* Wl1  = (const float*)d_in[2];
    const float* Wr1  = (const float*)d_in[3];
    const float* b1   = (const float*)d_in[4];
    const float* Wlm  = (const float*)d_in[5];   // [8,5,5]
    const float* Wrm  = (const float*)d_in[6];   // [8,5,5]
    const float* bm   = (const float*)d_in[7];   // [8,5]
    const float* Wl10 = (const float*)d_in[8];   // [1,5]
    const float* Wr10 = (const float*)d_in[9];   // [1,5]
    const float* b10  = (const float*)d_in[10];  // [1]
    float* out = (float*)d_out;

    void *pa, *pb, *sa, *sb_, *pcnt;
    cudaGetSymbolAddress(&pa,   g_pa);
    cudaGetSymbolAddress(&pb,   g_pb);
    cudaGetSymbolAddress(&sa,   g_sa);
    cudaGetSymbolAddress(&sb_,  g_sb);
    cudaGetSymbolAddress(&pcnt, g_cnt);
    float* P[2] = { (float*)pa,  (float*)pb  };
    float* S[2] = { (float*)sa,  (float*)sb_ };

    const int E = N_EDGES;
    int e4blocks = (E / 4 + 255) / 256;      // fill blocks (256 threads)
    int nb       = (N_NODES + 255) / 256;    // proj blocks
    int npairs   = N_NODES / 2;
    int ablocks  = (npairs + 3) / 4;         // 2 nodes/warp, 4 warps/block (128 thr)

    cudaMemsetAsync(pcnt, 0, N_NODES * sizeof(int));
    k_build<<<e4blocks + nb, 256>>>(ei, E, e4blocks, x, Wl1, Wr1, b1, P[0], S[0]);

    // layer 0: CSR is dependent -> early wait variant
    launch_pdl(k_agg5<5, false>, ablocks, 128,
               (const float*)P[0], (const float*)S[0], P[1], S[1],
               Wlm + 0 * 25, Wrm + 0 * 25, bm + 0 * 5);
    int cur = 1;
    // layers 1..7: CSR immutable -> late wait (prologue overlaps prev tail)
    for (int L = 1; L <= 7; ++L) {
        launch_pdl(k_agg5<5, true>, ablocks, 128,
                   (const float*)P[cur], (const float*)S[cur], P[1 - cur], S[1 - cur],
                   Wlm + L * 25, Wrm + L * 25, bm + L * 5);
        cur = 1 - cur;
    }
    // layer 8: pre-project scalar p9/self9 with Wl10/Wr10/b10
    launch_pdl(k_agg5<1, true>, ablocks, 128,
               (const float*)P[cur], (const float*)S[cur], P[1 - cur], S[1 - cur],
               Wl10, Wr10, b10);
    cur = 1 - cur;
    // layer 9 (final, no relu): out = mean(p9) + self9
    launch_pdl(k_agg_final, ablocks, 128,
               (const float*)P[cur], (const float*)S[cur], out);
}